// round 17
// baseline (speedup 1.0000x reference)
#include <cuda_runtime.h>
#include <cuda_bf16.h>
#include <cstdint>

// Problem constants (LangevinSDEContiformer: B=1024, S=512, H=64, D_IN=3)
#define BB   1024
#define SS   512
#define HH   64
#define DIN  3
#define SM1  511    // S-1 steps

__device__ float d_sigsc[SM1 * HH];
__device__ float d_hstep[SM1];
__device__ float d_times[SM1];

__global__ void sigma_kernel(const float* __restrict__ ts,
                             const float* __restrict__ Wd1, const float* __restrict__ bd1,
                             const float* __restrict__ Wd2, const float* __restrict__ bd2,
                             const float* __restrict__ minp, const float* __restrict__ maxp)
{
    __shared__ float hh[32];
    int s = blockIdx.x;
    int tid = threadIdx.x;
    float t = ts[(size_t)s * DIN];
    if (tid < 32) hh[tid] = fmaxf(t * Wd1[tid] + bd1[tid], 0.0f);
    __syncthreads();
    float acc = bd2[tid];
    #pragma unroll
    for (int i = 0; i < 32; i++) acc += hh[i] * Wd2[i * HH + tid];
    float sp = fmaxf(acc, 0.0f) + log1pf(expf(-fabsf(acc)));
    float mind = fabsf(minp[0]);
    float maxd = fabsf(maxp[0]);
    float sig = fminf(fmaxf(sp + mind, mind), maxd);
    float hs = ts[(size_t)(s + 1) * DIN] - t;
    d_sigsc[s * HH + tid] = sig * sqrtf(hs);
    if (tid == 0) { d_hstep[s] = hs; d_times[s] = t; }
}

typedef unsigned int u32;

__device__ __forceinline__ u32 packbf(float lo, float hi) {
    u32 r;
    asm("cvt.rn.bf16x2.f32 %0, %1, %2;" : "=r"(r) : "f"(hi), "f"(lo));
    return r;
}
__device__ __forceinline__ float tanh_fast(float x) {
    float y;
    asm("tanh.approx.f32 %0, %1;" : "=f"(y) : "f"(x));
    return y;
}
// mma.m16n8k16 row.col bf16 -> f32.  C layout (16x8):
//   c0:(row=lane/4, col=(lane%4)*2) c1:(.., col+1) c2:(row+8, col) c3:(row+8, col+1)
__device__ __forceinline__ void mma16816(float* c, uint4 a, u32 b0, u32 b1) {
    asm volatile(
        "mma.sync.aligned.m16n8k16.row.col.f32.bf16.bf16.f32 "
        "{%0,%1,%2,%3}, {%4,%5,%6,%7}, {%8,%9}, {%0,%1,%2,%3};"
        : "+f"(c[0]), "+f"(c[1]), "+f"(c[2]), "+f"(c[3])
        : "r"(a.x), "r"(a.y), "r"(a.z), "r"(a.w), "r"(b0), "r"(b1));
}

// Activation word (f2, r) -> storage slot (u32 index) in paired layout:
// consumer for kc loads uint2 at ((kc*4 + (lane&3))*8 + lq)*2 getting
// words j=(lane&3) and j=(lane&3)+4 of that kc block.
__device__ __forceinline__ int act_slot(int f2, int r) {
    int kc = f2 >> 3, j = f2 & 7;
    return ((kc * 4 + (j & 3)) * 8 + r) * 2 + (j >> 2);
}

// ---------------------------------------------------------------------------
// Transposed tensor-core scan.  128 CTAs x 256 thr; 2 groups x (4 warps, 4 rows).
// C tiles = [16 out-features x 8 batch-rows] (rows 4..7 padding).
// Register-only epilogues; 4 group barriers/step; depth-2 mma chains;
// LDS.64 B-fragment loads; all loop-invariant constants hoisted.
// ---------------------------------------------------------------------------
#define OFF_AF    0                        // 128 frags x 32 lanes x uint4 = 16384 u32
#define OFF_ACT   16384                    // per group 1536 u32
#define ACT_G     1536
#define AOFF_Y    0
#define AOFF_H    256
#define AOFF_G2   768
#define AOFF_G1   1024
#define OFF_F32   (OFF_ACT + 2*ACT_G)
#define OFF_W1T   (OFF_F32)                // [128] f32
#define OFF_B1    (OFF_W1T + 128)
#define OFF_B2    (OFF_B1 + 128)           // [64]
#define OFF_W3    (OFF_B2 + 64)            // [64]
#define OFF_YF    (OFF_W3 + 64)            // [2][64][8] f32 = 1024
#define SMEM_U32  (OFF_YF + 1024)
#define SMEM_BYTES (SMEM_U32 * 4)          // 83456

__global__ void __launch_bounds__(256, 1)
sde_scan_kernel(const float* __restrict__ ts, const float* __restrict__ noise,
                const float* __restrict__ Wp1, const float* __restrict__ bp1,
                const float* __restrict__ Wp2, const float* __restrict__ bp2,
                const float* __restrict__ Wp3, float* __restrict__ out)
{
    extern __shared__ u32 smu[];
    uint4* AF = (uint4*)smu;               // [128 frags][32 lanes]
    float* W1t = (float*)(smu + OFF_W1T);
    float* B1s = (float*)(smu + OFF_B1);
    float* B2s = (float*)(smu + OFF_B2);
    float* W3s = (float*)(smu + OFF_W3);

    const int tid  = threadIdx.x;
    const int lane = tid & 31;
    const int w    = tid >> 5;
    const int g    = w >> 2;               // group 0/1
    const int c    = w & 3;                // warp role in group
    const int rowTop = blockIdx.x * 8;
    const int gbar = 1 + g;

    u32* ActY  = smu + OFF_ACT + g * ACT_G + AOFF_Y;   // paired layout, 256 words
    u32* ActH  = smu + OFF_ACT + g * ACT_G + AOFF_H;   // 512 words
    u32* ActG2 = smu + OFF_ACT + g * ACT_G + AOFF_G2;  // 256 words
    u32* ActG1 = smu + OFF_ACT + g * ACT_G + AOFF_G1;  // 512 words
    __nv_bfloat16* ActHb  = (__nv_bfloat16*)ActH;
    __nv_bfloat16* ActG2b = (__nv_bfloat16*)ActG2;
    __nv_bfloat16* ActG1b = (__nv_bfloat16*)ActG1;
    __nv_bfloat16* ActYb  = (__nv_bfloat16*)ActY;
    float* Yf = (float*)(smu + OFF_YF) + g * 512;      // [64 f][8 r]

    // ---- build weight A-fragments (128 frags), phase p: frag = p*32 + mt*KC + kc
    for (int fi = w; fi < 128; fi += 8) {
        int ph = fi >> 5, loc = fi & 31;
        int KC = (ph == 0 || ph == 2) ? 4 : 8;
        int mt = loc / KC, kc = loc % KC;
        int r0 = mt * 16 + (lane >> 2);
        int c0 = kc * 16 + (lane & 3) * 2;
        float v[2][4];
        #pragma unroll
        for (int rh = 0; rh < 2; rh++) {
            int m = r0 + rh * 8;
            #pragma unroll
            for (int cc = 0; cc < 4; cc++) {
                int k = c0 + (cc >> 1) * 8 + (cc & 1);
                float x;
                if (ph == 0)      x = Wp1[k * 128 + m];
                else if (ph == 1) x = Wp2[k * 64 + m];
                else if (ph == 2) x = Wp2[m * 64 + k];
                else              x = Wp1[m * 128 + k];
                v[rh][cc] = x;
            }
        }
        uint4 fr;
        fr.x = packbf(v[0][0], v[0][1]);
        fr.y = packbf(v[1][0], v[1][1]);
        fr.z = packbf(v[0][2], v[0][3]);
        fr.w = packbf(v[1][2], v[1][3]);
        AF[fi * 32 + lane] = fr;
    }
    if (tid < 128) { W1t[tid] = Wp1[64 * 128 + tid]; B1s[tid] = bp1[tid]; }
    if (tid < 64)  { B2s[tid] = bp2[tid]; W3s[tid] = Wp3[tid]; }

    // ---- init ActY (paired layout), Yf, out[:,0,:]
    for (int idx = tid; idx < 512; idx += 256) {
        int gg = idx >> 8, ww = idx & 255;
        int f2 = ww >> 3, r = ww & 7;
        float v0 = 0.f, v1 = 0.f;
        if (r < 4) {
            int b = rowTop + gg * 4 + r;
            if (2 * f2 < DIN)     v0 = ts[(size_t)b * SS * DIN + 2 * f2];
            if (2 * f2 + 1 < DIN) v1 = ts[(size_t)b * SS * DIN + 2 * f2 + 1];
        }
        smu[OFF_ACT + gg * ACT_G + AOFF_Y + act_slot(f2, r)] = packbf(v0, v1);
    }
    for (int idx = tid; idx < 1024; idx += 256) {
        int gg = idx >> 9, ww = idx & 511;
        int f = ww >> 3, r = ww & 7;
        float v = 0.f;
        if (r < 4 && f < DIN) v = ts[(size_t)(rowTop + gg * 4 + r) * SS * DIN + f];
        ((float*)(smu + OFF_YF))[gg * 512 + ww] = v;
    }
    for (int idx = tid; idx < 512; idx += 256) {
        int r8 = idx >> 6, k = idx & 63;
        int b = rowTop + r8;
        out[((size_t)b * SS) * HH + k] = (k < DIN) ? ts[(size_t)b * SS * DIN + k] : 0.f;
    }
    __syncthreads();

    const int lq  = lane >> 2;             // 0..7
    const int lr2 = (lane & 3) * 2;        // 0,2,4,6
    const int bbase = ((lane & 3) * 8 + lq) * 2;   // B-load base (uint2 index /2)

    // ---- hoist loop-invariant per-thread constants ----
    // P1: f = 32c + 16t + lq + 8h  (t,h in {0,1})
    float w1tv[4], b1v[4];
    int idxH[8];                            // bf16 element index for (t,h=q>>1,q&1 row)
    #pragma unroll
    for (int t = 0; t < 2; t++)
        #pragma unroll
        for (int h = 0; h < 2; h++) {
            int f = 32 * c + 16 * t + lq + 8 * h;
            w1tv[t * 2 + h] = W1t[f];
            b1v[t * 2 + h]  = B1s[f];
            #pragma unroll
            for (int rr = 0; rr < 2; rr++)
                idxH[t * 4 + h * 2 + rr] = act_slot(f >> 1, lr2 + rr) * 2 + (f & 1);
        }
    // P2/P4/E4: f = 16c + lq + 8h
    float b2v[2], w3v[2];
    int idxG2[4], idxY[4];
    size_t outb[4];
    #pragma unroll
    for (int h = 0; h < 2; h++) {
        int f = 16 * c + lq + 8 * h;
        b2v[h] = B2s[f];
        w3v[h] = W3s[f];
        #pragma unroll
        for (int rr = 0; rr < 2; rr++) {
            idxG2[h * 2 + rr] = act_slot(f >> 1, lr2 + rr) * 2 + (f & 1);
            idxY[h * 2 + rr]  = idxG2[h * 2 + rr];   // same geometry (KK=64)
            int r = lr2 + rr;
            outb[h * 2 + rr] = (r < 4)
                ? ((size_t)(rowTop + g * 4 + r) * SS) * HH + f : (size_t)0;
        }
    }
    // P3 writes G1 (KK=128) at same f as P1
    int idxG1[8];
    #pragma unroll
    for (int t = 0; t < 2; t++)
        #pragma unroll
        for (int h = 0; h < 2; h++) {
            int f = 32 * c + 16 * t + lq + 8 * h;
            #pragma unroll
            for (int rr = 0; rr < 2; rr++)
                idxG1[t * 4 + h * 2 + rr] = act_slot(f >> 1, lr2 + rr) * 2 + (f & 1);
        }
    // Yf positions for E4: f*8 + r
    int idxYf[4];
    #pragma unroll
    for (int h = 0; h < 2; h++)
        #pragma unroll
        for (int rr = 0; rr < 2; rr++)
            idxYf[h * 2 + rr] = (16 * c + lq + 8 * h) * 8 + lr2 + rr;

    for (int s = 0; s < SM1; s++) {
        const float tcur  = d_times[s];
        const float hstep = d_hstep[s];

        // prefetch noise*sigma (E4 positions): q = h*2+rr
        float zsc[4];
        #pragma unroll
        for (int h = 0; h < 2; h++)
            #pragma unroll
            for (int rr = 0; rr < 2; rr++) {
                int f = 16 * c + lq + 8 * h;
                int r = lr2 + rr;
                zsc[h * 2 + rr] = (r < 4)
                    ? d_sigsc[s * HH + f] *
                      noise[((size_t)s * BB + rowTop + g * 4 + r) * HH + f]
                    : 0.f;
            }

        float h1v[8];

        // ===== P1: out j(128) = W1^T @ y. warp c: m-tiles {2c,2c+1}, K=64 ===
        {
            uint2 by[4];
            #pragma unroll
            for (int kc = 0; kc < 4; kc++)
                by[kc] = *(const uint2*)&ActY[bbase + kc * 64];
            #pragma unroll
            for (int t = 0; t < 2; t++) {
                float c0[4] = {0.f,0.f,0.f,0.f}, c1[4] = {0.f,0.f,0.f,0.f};
                mma16816(c0, AF[((2*c+t)*4 + 0) * 32 + lane], by[0].x, by[0].y);
                mma16816(c1, AF[((2*c+t)*4 + 1) * 32 + lane], by[1].x, by[1].y);
                mma16816(c0, AF[((2*c+t)*4 + 2) * 32 + lane], by[2].x, by[2].y);
                mma16816(c1, AF[((2*c+t)*4 + 3) * 32 + lane], by[3].x, by[3].y);
                #pragma unroll
                for (int q = 0; q < 4; q++) {
                    int h = q >> 1, rr = q & 1;
                    float v = (c0[q] + c1[q]) + fmaf(tcur, w1tv[t*2+h], b1v[t*2+h]);
                    float hh = tanh_fast(v);
                    h1v[t * 4 + q] = hh;
                    ActHb[idxH[t * 4 + h * 2 + rr]] = __float2bfloat16(hh);
                }
            }
        }
        asm volatile("bar.sync %0, %1;" :: "r"(gbar), "r"(128) : "memory");

        // ===== P2: out j2(64) = W2^T @ h1. warp c: m-tile c, K=128 ==========
        {
            uint2 bh[8];
            #pragma unroll
            for (int kc = 0; kc < 8; kc++)
                bh[kc] = *(const uint2*)&ActH[bbase + kc * 64];
            float a0[4] = {0.f,0.f,0.f,0.f}, a1[4] = {0.f,0.f,0.f,0.f};
            float a2[4] = {0.f,0.f,0.f,0.f}, a3[4] = {0.f,0.f,0.f,0.f};
            mma16816(a0, AF[(32 + c * 8 + 0) * 32 + lane], bh[0].x, bh[0].y);
            mma16816(a1, AF[(32 + c * 8 + 1) * 32 + lane], bh[1].x, bh[1].y);
            mma16816(a2, AF[(32 + c * 8 + 2) * 32 + lane], bh[2].x, bh[2].y);
            mma16816(a3, AF[(32 + c * 8 + 3) * 32 + lane], bh[3].x, bh[3].y);
            mma16816(a0, AF[(32 + c * 8 + 4) * 32 + lane], bh[4].x, bh[4].y);
            mma16816(a1, AF[(32 + c * 8 + 5) * 32 + lane], bh[5].x, bh[5].y);
            mma16816(a2, AF[(32 + c * 8 + 6) * 32 + lane], bh[6].x, bh[6].y);
            mma16816(a3, AF[(32 + c * 8 + 7) * 32 + lane], bh[7].x, bh[7].y);
            #pragma unroll
            for (int q = 0; q < 4; q++) {
                int h = q >> 1, rr = q & 1;
                float h2 = tanh_fast(((a0[q] + a1[q]) + (a2[q] + a3[q])) + b2v[h]);
                float g2 = w3v[h] * (1.0f - h2 * h2);
                ActG2b[idxG2[h * 2 + rr]] = __float2bfloat16(g2);
            }
        }
        asm volatile("bar.sync %0, %1;" :: "r"(gbar), "r"(128) : "memory");

        // ===== P3: out i(128) = W2 @ g2. warp c: m-tiles {2c,2c+1}, K=64 ====
        {
            uint2 bg[4];
            #pragma unroll
            for (int kc = 0; kc < 4; kc++)
                bg[kc] = *(const uint2*)&ActG2[bbase + kc * 64];
            #pragma unroll
            for (int t = 0; t < 2; t++) {
                float c0[4] = {0.f,0.f,0.f,0.f}, c1[4] = {0.f,0.f,0.f,0.f};
                mma16816(c0, AF[(64 + (2*c+t)*4 + 0) * 32 + lane], bg[0].x, bg[0].y);
                mma16816(c1, AF[(64 + (2*c+t)*4 + 1) * 32 + lane], bg[1].x, bg[1].y);
                mma16816(c0, AF[(64 + (2*c+t)*4 + 2) * 32 + lane], bg[2].x, bg[2].y);
                mma16816(c1, AF[(64 + (2*c+t)*4 + 3) * 32 + lane], bg[3].x, bg[3].y);
                #pragma unroll
                for (int q = 0; q < 4; q++) {
                    int h = q >> 1, rr = q & 1;
                    float h1 = h1v[t * 4 + q];
                    float g1 = (c0[q] + c1[q]) * (1.0f - h1 * h1);
                    ActG1b[idxG1[t * 4 + h * 2 + rr]] = __float2bfloat16(g1);
                }
            }
        }
        asm volatile("bar.sync %0, %1;" :: "r"(gbar), "r"(128) : "memory");

        // ===== P4: dy k(64) = W1 @ g1. warp c: m-tile c, K=128; update y ====
        {
            uint2 bg[8];
            #pragma unroll
            for (int kc = 0; kc < 8; kc++)
                bg[kc] = *(const uint2*)&ActG1[bbase + kc * 64];
            float a0[4] = {0.f,0.f,0.f,0.f}, a1[4] = {0.f,0.f,0.f,0.f};
            float a2[4] = {0.f,0.f,0.f,0.f}, a3[4] = {0.f,0.f,0.f,0.f};
            mma16816(a0, AF[(96 + c * 8 + 0) * 32 + lane], bg[0].x, bg[0].y);
            mma16816(a1, AF[(96 + c * 8 + 1) * 32 + lane], bg[1].x, bg[1].y);
            mma16816(a2, AF[(96 + c * 8 + 2) * 32 + lane], bg[2].x, bg[2].y);
            mma16816(a3, AF[(96 + c * 8 + 3) * 32 + lane], bg[3].x, bg[3].y);
            mma16816(a0, AF[(96 + c * 8 + 4) * 32 + lane], bg[4].x, bg[4].y);
            mma16816(a1, AF[(96 + c * 8 + 5) * 32 + lane], bg[5].x, bg[5].y);
            mma16816(a2, AF[(96 + c * 8 + 6) * 32 + lane], bg[6].x, bg[6].y);
            mma16816(a3, AF[(96 + c * 8 + 7) * 32 + lane], bg[7].x, bg[7].y);
            #pragma unroll
            for (int q = 0; q < 4; q++) {
                int h = q >> 1, rr = q & 1;
                float dy = (a0[q] + a1[q]) + (a2[q] + a3[q]);
                float ynew = fmaf(-dy, hstep, Yf[idxYf[q]]) + zsc[q];
                Yf[idxYf[q]] = ynew;
                ActYb[idxY[h * 2 + rr]] = __float2bfloat16(ynew);
                if (lr2 + rr < 4)
                    out[outb[q] + (size_t)(s + 1) * HH] = ynew;
            }
        }
        asm volatile("bar.sync %0, %1;" :: "r"(gbar), "r"(128) : "memory");
    }
}

// ---------------------------------------------------------------------------
extern "C" void kernel_launch(void* const* d_in, const int* in_sizes, int n_in,
                              void* d_out, int out_size)
{
    (void)in_sizes; (void)n_in; (void)out_size;
    const float* ts    = (const float*)d_in[0];   // time_series (B,S,3)
    const float* noise = (const float*)d_in[1];   // (S-1,B,H)
    const float* Wp1   = (const float*)d_in[2];   // (65,128)
    const float* bp1   = (const float*)d_in[3];   // (128,)
    const float* Wp2   = (const float*)d_in[4];   // (128,64)
    const float* bp2   = (const float*)d_in[5];   // (64,)
    const float* Wp3   = (const float*)d_in[6];   // (64,1)
    // d_in[7] = bp3 (unused: constant shift, zero gradient)
    const float* Wd1   = (const float*)d_in[8];   // (1,32)
    const float* bd1   = (const float*)d_in[9];   // (32,)
    const float* Wd2   = (const float*)d_in[10];  // (32,64)
    const float* bd2   = (const float*)d_in[11];  // (64,)
    const float* mn    = (const float*)d_in[12];  // scalar
    const float* mx    = (const float*)d_in[13];  // scalar
    float* out = (float*)d_out;

    cudaFuncSetAttribute(sde_scan_kernel,
                         cudaFuncAttributeMaxDynamicSharedMemorySize, SMEM_BYTES);

    sigma_kernel<<<SM1, HH>>>(ts, Wd1, bd1, Wd2, bd2, mn, mx);
    sde_scan_kernel<<<BB / 8, 256, SMEM_BYTES>>>(ts, noise, Wp1, bp1, Wp2, bp2, Wp3, out);
}